// round 12
// baseline (speedup 1.0000x reference)
#include <cuda_runtime.h>

#define Bx 4
#define Nn 2048
#define Dd 512
#define Hh 8
#define ZCH 128    // z chunks
#define ZR  16     // rows per z chunk
#define GRID 512
#define NTHR 256

// ---------------- device scratch ----------------
__device__ float g_u[Hh][Dd];
__device__ float g_ch[Hh];
__device__ float g_s0p[Hh][8];
__device__ float g_sc[Bx][Hh][Nn];
__device__ float g_nm[Bx][Hh];
__device__ float g_nrs[Bx][Hh];
__device__ float g_p0[Bx][Hh];
__device__ float g_zp[ZCH][Bx][Hh][Dd];
__device__ float g_z[Bx][Hh][Dd];
__device__ float g_w[Bx][Dd];
__device__ float g_y[Bx][Dd];
__device__ unsigned g_start = 0;                       // monotonic across replays
__device__ unsigned g_bar[8] = {0, 0, 0, 0, 0, 0, 0, 0};

__device__ __forceinline__ float warp_sum(float v) {
    #pragma unroll
    for (int o = 16; o; o >>= 1) v += __shfl_xor_sync(0xffffffffu, v, o);
    return v;
}
__device__ __forceinline__ float warp_max(float v) {
    #pragma unroll
    for (int o = 16; o; o >>= 1) v = fmaxf(v, __shfl_xor_sync(0xffffffffu, v, o));
    return v;
}
__device__ __forceinline__ float dot4(float4 a, float4 b) {
    return a.x * b.x + a.y * b.y + a.z * b.z + a.w * b.w;
}

// grid barrier: monotonic counter, target = GRID * replay_epoch
#define GBAR(i)                                                   \
    do {                                                          \
        __syncthreads();                                          \
        if (t == 0) {                                             \
            __threadfence();                                      \
            atomicAdd(&g_bar[i], 1u);                             \
            while (*(volatile unsigned*)&g_bar[i] < target) { }   \
            __threadfence();                                      \
        }                                                         \
        __syncthreads();                                          \
    } while (0)

__global__ void __launch_bounds__(NTHR, 4)
k_all(const float* __restrict__ nf, const float* __restrict__ masks,
      const float* __restrict__ ct,
      const float* __restrict__ Wq, const float* __restrict__ bq,
      const float* __restrict__ Wk, const float* __restrict__ bk,
      const float* __restrict__ Wv, const float* __restrict__ bv,
      const float* __restrict__ Wo, const float* __restrict__ bo,
      const float* __restrict__ gamma, const float* __restrict__ beta,
      float* __restrict__ out) {
    __shared__ __align__(16) float sm[4224];   // 16.5 KB union buffer
    __shared__ unsigned s_target;
    const int bid = blockIdx.x;
    const int t = threadIdx.x, wid = t >> 5, lane = t & 31;

    if (t == 0) s_target = ((atomicAdd(&g_start, 1u) >> 9) + 1u) * GRID;
    __syncthreads();
    const unsigned target = s_target;

    // ================= P0: prep (blocks 0..63): q0 slice, u, s0p, ch =================
    if (bid < 64) {
        const int h = bid >> 3, dc = bid & 7;
        float* cts = sm;            // 512
        float* q0s = sm + 512;      // 64
        float* red4 = sm + 576;     // 4*64
        float* red64 = sm + 832;    // 64
        cts[t] = ct[t]; cts[t + 256] = ct[t + 256];
        __syncthreads();
        {   // q0 slice: 8 warps x 8 rows
            const float4* cv = (const float4*)cts;
            #pragma unroll
            for (int rr = 0; rr < 8; rr++) {
                const int i = wid * 8 + rr;
                const float4* row = (const float4*)(Wq + (size_t)(h * 64 + i) * Dd);
                float s = 0.f;
                #pragma unroll
                for (int k = 0; k < 4; k++) s += dot4(row[lane + 32 * k], cv[lane + 32 * k]);
                s = warp_sum(s);
                if (lane == 0) q0s[i] = s + bq[h * 64 + i];
            }
        }
        __syncthreads();
        const int part = t >> 6, dl = t & 63;   // 4 partitions x 16 rows
        {
            const float* base = Wk + (size_t)(h * 64 + part * 16) * Dd + dc * 64 + dl;
            float acc = 0.f;
            #pragma unroll
            for (int i = 0; i < 16; i++) acc += q0s[part * 16 + i] * base[(size_t)i * Dd];
            red4[part * 64 + dl] = acc;
        }
        __syncthreads();
        if (t < 64) {
            const float u = red4[t] + red4[64 + t] + red4[128 + t] + red4[192 + t];
            g_u[h][dc * 64 + t] = u;
            red64[t] = u * cts[dc * 64 + t];
        }
        __syncthreads();
        if (t < 32) {
            float v = red64[t] + red64[t + 32];
            v = warp_sum(v);
            if (t == 0) g_s0p[h][dc] = v;
            if (dc == 0) {
                float cvv = q0s[t] * bk[h * 64 + t] + q0s[t + 32] * bk[h * 64 + t + 32];
                cvv = warp_sum(cvv);
                if (t == 0) g_ch[h] = cvv;
            }
        }
    }
    GBAR(0);

    // ================= P1: scores (all 512): warp = 2 rows, 8 heads =================
    {
        const int c = bid >> 2, b = bid & 3;
        float4* us4 = (float4*)sm;          // 1024 float4 = 16 KB
        float* chs = sm + 4096;             // 8
        {
            const float4* uf = (const float4*)&g_u[0][0];
            #pragma unroll
            for (int k = 0; k < 4; k++) us4[t + k * 256] = uf[t + k * 256];
            if (t < Hh) chs[t] = g_ch[t];
        }
        __syncthreads();
        const int n0 = c * 16 + wid * 2;
        const float4* x4 = (const float4*)(nf + ((size_t)b * Nn + n0) * Dd);
        float4 xr0[4], xr1[4];
        #pragma unroll
        for (int k = 0; k < 4; k++) { xr0[k] = x4[lane + 32 * k]; xr1[k] = x4[128 + lane + 32 * k]; }
        const float mv0 = masks[(size_t)b * Nn + n0];
        const float mv1 = masks[(size_t)b * Nn + n0 + 1];
        #pragma unroll
        for (int h = 0; h < Hh; h++) {
            float s0 = 0.f, s1 = 0.f;
            #pragma unroll
            for (int k = 0; k < 4; k++) {
                const float4 uv = us4[h * 128 + lane + 32 * k];
                s0 += dot4(uv, xr0[k]);
                s1 += dot4(uv, xr1[k]);
            }
            s0 = warp_sum(s0);
            s1 = warp_sum(s1);
            if (lane == 0) {
                float v0 = (s0 + chs[h]) * 0.125f;
                float v1 = (s1 + chs[h]) * 0.125f;
                if (mv0 * mv0 == 0.f) v0 = -1e9f;
                if (mv1 * mv1 == 0.f) v1 = -1e9f;
                g_sc[b][h][n0] = v0;
                g_sc[b][h][n0 + 1] = v1;
            }
        }
    }
    GBAR(1);

    // ================= P2: softmax stats (blocks 0..31) =================
    if (bid < 32) {
        const int b = bid >> 3, h = bid & 7;
        float* red = sm;
        float vloc[8];
        float m = -3e38f;
        #pragma unroll
        for (int k = 0; k < 8; k++) {
            vloc[k] = g_sc[b][h][t + 256 * k];
            m = fmaxf(m, vloc[k]);
        }
        m = warp_max(m);
        if (lane == 0) red[wid] = m;
        __syncthreads();
        if (t == 0) {
            float M = fmaxf(fmaxf(fmaxf(red[0], red[1]), fmaxf(red[2], red[3])),
                            fmaxf(fmaxf(red[4], red[5]), fmaxf(red[6], red[7])));
            float sp = 0.f;
            #pragma unroll
            for (int dc = 0; dc < 8; dc++) sp += g_s0p[h][dc];
            const float s0 = (sp + g_ch[h]) * 0.125f;
            M = fmaxf(M, s0);
            red[16] = M;
            red[17] = s0;
        }
        __syncthreads();
        const float M = red[16], s0 = red[17];
        float e = 0.f;
        #pragma unroll
        for (int k = 0; k < 8; k++) e += expf(vloc[k] - M);
        e = warp_sum(e);
        if (lane == 0) red[24 + wid] = e;
        __syncthreads();
        if (t == 0) {
            float x = 0.f;
            #pragma unroll
            for (int w = 0; w < 8; w++) x += red[24 + w];
            const float S = x + expf(s0 - M);
            g_nm[b][h] = M;
            g_nrs[b][h] = 1.f / S;
            g_p0[b][h] = expf(s0 - M) / S;
        }
    }
    GBAR(2);

    // ================= P3: z partials (all 512): 16 rows, float2 dims =================
    {
        const int c = bid >> 2, b = bid & 3;
        float* ps = sm;                     // [Hh][ZR] = 128
        if (t < Hh * ZR) {
            const int h = t >> 4, jj = t & 15;
            ps[h * ZR + jj] = expf(g_sc[b][h][c * ZR + jj] - g_nm[b][h]) * g_nrs[b][h];
        }
        __syncthreads();
        float2 acc[Hh];
        #pragma unroll
        for (int h = 0; h < Hh; h++) acc[h] = make_float2(0.f, 0.f);
        const float2* xp = (const float2*)(nf + ((size_t)b * Nn + c * ZR) * Dd) + t;
        #pragma unroll
        for (int jj = 0; jj < ZR; jj++) {
            const float2 xv = xp[jj * 256];
            #pragma unroll
            for (int h = 0; h < Hh; h++) {
                const float p = ps[h * ZR + jj];
                acc[h].x += p * xv.x;
                acc[h].y += p * xv.y;
            }
        }
        #pragma unroll
        for (int h = 0; h < Hh; h++)
            ((float2*)&g_zp[c][b][h][0])[t] = acc[h];
    }
    GBAR(3);

    // ================= P4: reduce partials (blocks 0..63) =================
    if (bid < 64) {
        const int b = bid >> 4, h = (bid >> 1) & 7, half = bid & 1;
        const int d = half * 256 + t;
        float acc = g_p0[b][h] * ct[d];
        #pragma unroll 8
        for (int c = 0; c < ZCH; c++) acc += g_zp[c][b][h][d];
        g_z[b][h][d] = acc;
    }
    GBAR(4);

    // ================= P5: Wv GEMV (blocks 0..63): Wv read once =================
    if (bid < 64) {
        const int h = bid >> 3, rg = bid & 7;
        float* zs = sm;                     // [Bx][Dd] = 2048
        #pragma unroll
        for (int idx = t; idx < Bx * Dd; idx += NTHR) {
            const int b = idx >> 9, d = idx & 511;
            zs[b * Dd + d] = g_z[b][h][d];
        }
        __syncthreads();
        const int i = h * 64 + rg * 8 + wid;
        const float4* row = (const float4*)(Wv + (size_t)i * Dd);
        float4 rv[4];
        #pragma unroll
        for (int k = 0; k < 4; k++) rv[k] = row[lane + 32 * k];
        #pragma unroll
        for (int b = 0; b < Bx; b++) {
            float s = 0.f;
            #pragma unroll
            for (int k = 0; k < 4; k++)
                s += dot4(rv[k], ((const float4*)(zs + b * Dd))[lane + 32 * k]);
            s = warp_sum(s);
            if (lane == 0) g_w[b][i] = s + bv[i];
        }
    }
    GBAR(5);

    // ================= P6: Wo GEMV (blocks 0..255): warp = (row, batch) =================
    if (bid < 256) {
        float4* ws4 = (float4*)sm;          // 512 float4 = 8 KB
        {
            const float4* gw4 = (const float4*)&g_w[0][0];
            ws4[t] = gw4[t];
            ws4[t + 256] = gw4[t + 256];
        }
        __syncthreads();
        const int gw = bid * 8 + wid;
        const int r = gw >> 2, b = gw & 3;
        const float4* row = (const float4*)(Wo + (size_t)r * Dd);
        float s = 0.f;
        #pragma unroll
        for (int k = 0; k < 4; k++) s += dot4(row[lane + 32 * k], ws4[b * 128 + lane + 32 * k]);
        s = warp_sum(s);
        if (lane == 0) g_y[b][r] = s + bo[r] + ct[r];
    }

    // ================= final barrier: arrive-all; blocks 0..3 do LayerNorm =================
    __syncthreads();
    if (t == 0) { __threadfence(); atomicAdd(&g_bar[6], 1u); }
    if (bid >= Bx) return;
    if (t == 0) {
        while (*(volatile unsigned*)&g_bar[6] < target) { }
        __threadfence();
    }
    __syncthreads();
    {
        const int b = bid;
        float* red = sm;
        const float y0 = g_y[b][t], y1 = g_y[b][t + 256];
        red[t] = y0 + y1;
        __syncthreads();
        for (int o = 128; o; o >>= 1) { if (t < o) red[t] += red[t + o]; __syncthreads(); }
        const float mu = red[0] * (1.f / Dd);
        __syncthreads();
        const float d0 = y0 - mu, d1 = y1 - mu;
        red[t] = d0 * d0 + d1 * d1;
        __syncthreads();
        for (int o = 128; o; o >>= 1) { if (t < o) red[t] += red[t + o]; __syncthreads(); }
        const float rs = rsqrtf(red[0] * (1.f / Dd) + 1e-5f);
        out[(size_t)b * Dd + t]       = d0 * rs * gamma[t] + beta[t];
        out[(size_t)b * Dd + t + 256] = d1 * rs * gamma[t + 256] + beta[t + 256];
    }
}

// ---------------- launcher ----------------
extern "C" void kernel_launch(void* const* d_in, const int* in_sizes, int n_in,
                              void* d_out, int out_size) {
    const float* nf    = (const float*)d_in[0];
    // d_in[1] edge_weights, d_in[2] adj_matrix: dead for CLS-row output
    const float* masks = (const float*)d_in[3];
    const float* ct    = (const float*)d_in[4];
    const float* Wq    = (const float*)d_in[5];
    const float* bq    = (const float*)d_in[6];
    const float* Wk    = (const float*)d_in[7];
    const float* bk    = (const float*)d_in[8];
    const float* Wv    = (const float*)d_in[9];
    const float* bv    = (const float*)d_in[10];
    const float* Wo    = (const float*)d_in[11];
    const float* bo    = (const float*)d_in[12];
    const float* gamma = (const float*)d_in[13];
    const float* beta  = (const float*)d_in[14];
    float* out = (float*)d_out;

    k_all<<<GRID, NTHR>>>(nf, masks, ct, Wq, bq, Wk, bk, Wv, bv,
                          Wo, bo, gamma, beta, out);
}